// round 1
// baseline (speedup 1.0000x reference)
#include <cuda_runtime.h>

#define NW   8
#define NH   8
#define EMB  64
#define DK   8
#define BB   8
#define SS   1024
#define BH   (BB * NH)          // 64
#define ROWS (BB * SS * NH)     // 65536

// Scratch (allocation-free rule: device globals)
__device__ float g_proj[BH * SS * DK];  // [b][h][s][d]  2 MB
__device__ float g_ao  [BH * SS * DK];  // attention out 2 MB

// ---------------------------------------------------------------------------
// Kernel A: quantum layer == prefix products of cos(x + phi)
//   proj[m][t] = prod_{w=0..t} cos(a_w)  (t>=1),  proj[m][0] = prod_{w=1..7} cos(a_w)
// ---------------------------------------------------------------------------
__global__ void qlayer_kernel(const float* __restrict__ x,
                              const float* __restrict__ phi) {
    int m = blockIdx.x * blockDim.x + threadIdx.x;
    if (m >= ROWS) return;
    // m = (b*SS + s)*NH + h
    int h  = m & 7;
    int bs = m >> 3;
    int s  = bs & (SS - 1);
    int b  = bs >> 10;

    float4 xa = ((const float4*)x)[m * 2];
    float4 xb = ((const float4*)x)[m * 2 + 1];

    float c0 = cosf(xa.x + phi[0]);
    float c1 = cosf(xa.y + phi[1]);
    float c2 = cosf(xa.z + phi[2]);
    float c3 = cosf(xa.w + phi[3]);
    float c4 = cosf(xb.x + phi[4]);
    float c5 = cosf(xb.y + phi[5]);
    float c6 = cosf(xb.z + phi[6]);
    float c7 = cosf(xb.w + phi[7]);

    float p1 = c0 * c1;
    float p2 = p1 * c2;
    float p3 = p2 * c3;
    float p4 = p3 * c4;
    float p5 = p4 * c5;
    float p6 = p5 * c6;
    float p7 = p6 * c7;
    // element 0: product of c1..c7
    float t  = c1 * c2;
    t *= c3; t *= c4; t *= c5; t *= c6; t *= c7;

    float4* o = (float4*)&g_proj[(((b * NH + h) * SS) + s) * DK];
    o[0] = make_float4(t,  p1, p2, p3);
    o[1] = make_float4(p4, p5, p6, p7);
}

// ---------------------------------------------------------------------------
// Kernel B: attention per (b,h).  K == V == proj[b][h].  Scores bounded by
// 8/sqrt(8)=2.83 -> no max-subtraction needed, plain sum-of-exp softmax.
// Grid: (BH, 2), block 256 threads, each thread owns 2 q rows.
// ---------------------------------------------------------------------------
__global__ __launch_bounds__(256) void attn_kernel() {
    __shared__ float sk[SS * DK];           // 32 KB: full K/V tile
    float4* sk4 = (float4*)sk;

    int bh = blockIdx.x;
    const float4* P4 = (const float4*)&g_proj[bh * SS * DK];

    #pragma unroll
    for (int i = 0; i < 8; i++)
        sk4[threadIdx.x + i * 256] = P4[threadIdx.x + i * 256];
    __syncthreads();

    const float scale = 0.35355339059327373f;  // 1/sqrt(DK)
    int r0 = blockIdx.y * 512 + threadIdx.x * 2;
    int r1 = r0 + 1;

    float q0[8], q1[8];
    #pragma unroll
    for (int d = 0; d < 8; d++) {
        q0[d] = sk[r0 * 8 + d] * scale;
        q1[d] = sk[r1 * 8 + d] * scale;
    }

    float acc0[8], acc1[8];
    #pragma unroll
    for (int d = 0; d < 8; d++) { acc0[d] = 0.f; acc1[d] = 0.f; }
    float l0 = 0.f, l1 = 0.f;

    #pragma unroll 4
    for (int j = 0; j < SS; j++) {
        float4 ka = sk4[j * 2];       // broadcast across warp: conflict-free
        float4 kb = sk4[j * 2 + 1];
        float k0 = ka.x, k1 = ka.y, k2 = ka.z, k3 = ka.w;
        float k4 = kb.x, k5 = kb.y, k6 = kb.z, k7 = kb.w;

        // split dots: two chains of 4 per row -> ILP 4 (x2 rows)
        float a0 = q0[0]*k0 + q0[1]*k1 + q0[2]*k2 + q0[3]*k3;
        float b0 = q0[4]*k4 + q0[5]*k5 + q0[6]*k6 + q0[7]*k7;
        float a1 = q1[0]*k0 + q1[1]*k1 + q1[2]*k2 + q1[3]*k3;
        float b1 = q1[4]*k4 + q1[5]*k5 + q1[6]*k6 + q1[7]*k7;

        float p0 = __expf(a0 + b0);
        float p1 = __expf(a1 + b1);
        l0 += p0;
        l1 += p1;

        acc0[0] += p0 * k0; acc1[0] += p1 * k0;
        acc0[1] += p0 * k1; acc1[1] += p1 * k1;
        acc0[2] += p0 * k2; acc1[2] += p1 * k2;
        acc0[3] += p0 * k3; acc1[3] += p1 * k3;
        acc0[4] += p0 * k4; acc1[4] += p1 * k4;
        acc0[5] += p0 * k5; acc1[5] += p1 * k5;
        acc0[6] += p0 * k6; acc1[6] += p1 * k6;
        acc0[7] += p0 * k7; acc1[7] += p1 * k7;
    }

    float inv0 = 1.f / l0;
    float inv1 = 1.f / l1;
    float4* ao4 = (float4*)&g_ao[(bh * SS + r0) * DK];
    ao4[0] = make_float4(acc0[0]*inv0, acc0[1]*inv0, acc0[2]*inv0, acc0[3]*inv0);
    ao4[1] = make_float4(acc0[4]*inv0, acc0[5]*inv0, acc0[6]*inv0, acc0[7]*inv0);
    ao4[2] = make_float4(acc1[0]*inv1, acc1[1]*inv1, acc1[2]*inv1, acc1[3]*inv1);
    ao4[3] = make_float4(acc1[4]*inv1, acc1[5]*inv1, acc1[6]*inv1, acc1[7]*inv1);
}

// ---------------------------------------------------------------------------
// Kernel C: gather heads + out = ao @ W^T + b.
// Block: 256 threads = 4 rows x 64 outputs. W transposed in smem so the
// inner reads are conflict-free (Wt[f][e], lanes e consecutive).
// ---------------------------------------------------------------------------
__global__ __launch_bounds__(256) void epilogue_kernel(const float* __restrict__ W,
                                                       const float* __restrict__ bias,
                                                       float* __restrict__ out) {
    __shared__ float sWt[64 * 64];   // Wt[f][e] = W[e][f]
    __shared__ float sin_[4 * 64];

    int tid = threadIdx.x;
    for (int i = tid; i < 64 * 64; i += 256) {
        int e = i >> 6, f = i & 63;
        sWt[f * 64 + e] = W[i];
    }

    int row0 = blockIdx.x * 4;
    {
        int r = tid >> 6, f = tid & 63;
        int row = row0 + r;
        int b = row >> 10, s = row & 1023;
        // feature f = h*8 + d lives at g_ao[((b*8+h)*1024+s)*8 + d]
        sin_[tid] = g_ao[(((b * 8 + (f >> 3)) * 1024 + s) << 3) + (f & 7)];
    }
    __syncthreads();

    int r = tid >> 6, e = tid & 63;
    float acc = bias[e];
    #pragma unroll
    for (int f = 0; f < 64; f++)
        acc += sin_[r * 64 + f] * sWt[f * 64 + e];   // sin_: broadcast, sWt: coalesced
    out[(row0 + r) * 64 + e] = acc;
}

// ---------------------------------------------------------------------------
extern "C" void kernel_launch(void* const* d_in, const int* in_sizes, int n_in,
                              void* d_out, int out_size) {
    const float* x    = (const float*)d_in[0];
    const float* phi  = (const float*)d_in[1];
    const float* W    = (const float*)d_in[2];
    const float* bias = (const float*)d_in[3];
    float* out = (float*)d_out;

    qlayer_kernel<<<ROWS / 256, 256>>>(x, phi);
    attn_kernel<<<dim3(BH, 2), 256>>>();
    epilogue_kernel<<<(BB * SS) / 4, 256>>>(W, bias, out);
}

// round 3
// speedup vs baseline: 1.0741x; 1.0741x over previous
#include <cuda_runtime.h>

#define DK   8
#define SS   1024
#define BB   8
#define NH   8
#define BH   (BB * NH)          // 64

// Scratch (allocation-free rule: device globals)
__device__ float g_ao[BH * SS * DK];   // attention out, [b][h][s][d]  2 MB

// ---------------------------------------------------------------------------
// f32x2 packed-math helpers (sm_10x). PTX f32x2 ops take untyped .b64 regs ->
// must use "l" (u64) constraints, NOT "d" (f64). Matches ptx_helpers.cuh.
// ---------------------------------------------------------------------------
typedef unsigned long long u64;

__device__ __forceinline__ u64 ffma2(u64 a, u64 b, u64 c) {
    u64 r; asm("fma.rn.f32x2 %0,%1,%2,%3;" : "=l"(r) : "l"(a), "l"(b), "l"(c)); return r;
}
__device__ __forceinline__ u64 fmul2(u64 a, u64 b) {
    u64 r; asm("mul.rn.f32x2 %0,%1,%2;" : "=l"(r) : "l"(a), "l"(b)); return r;
}
__device__ __forceinline__ u64 fadd2(u64 a, u64 b) {
    u64 r; asm("add.rn.f32x2 %0,%1,%2;" : "=l"(r) : "l"(a), "l"(b)); return r;
}
__device__ __forceinline__ u64 pk2(float lo, float hi) {
    u64 r; asm("mov.b64 %0,{%1,%2};" : "=l"(r) : "f"(lo), "f"(hi)); return r;
}
__device__ __forceinline__ void upk2(u64 v, float& lo, float& hi) {
    asm("mov.b64 {%0,%1},%2;" : "=f"(lo), "=f"(hi) : "l"(v));
}
__device__ __forceinline__ float ex2(float x) {
    float r; asm("ex2.approx.f32 %0,%1;" : "=f"(r) : "f"(x)); return r;
}

// ---------------------------------------------------------------------------
// Fused qlayer + attention per (b,h).
//   qlayer == prefix products of cos(x+phi) (Heisenberg reduction of the
//   8-qubit circuit).  K == V == proj.  |score| <= 8/sqrt(8) -> no max-sub.
//   q is pre-scaled by (1/sqrt(8))*log2(e) so softmax uses raw ex2.approx.
//   K tile stored TRANSPOSED in smem ([d][j]) so key-pairs (j,j+1) are
//   natural aligned f32x2 operands; all inner-loop LDS are warp-broadcast.
// Grid: (64 bh, 2 q-halves), 256 threads, 2 q-rows per thread.
// ---------------------------------------------------------------------------
__global__ __launch_bounds__(256) void attn_kernel(const float* __restrict__ x,
                                                   const float* __restrict__ phi) {
    __shared__ float smt[8 * SS];        // 32 KB, smt[d*1024 + j]

    const int bh = blockIdx.x;
    const int b = bh >> 3, h = bh & 7;
    const int tid = threadIdx.x;

    float ph0 = phi[0], ph1 = phi[1], ph2 = phi[2], ph3 = phi[3];
    float ph4 = phi[4], ph5 = phi[5], ph6 = phi[6], ph7 = phi[7];

    // ---- prologue: quantum layer straight into transposed smem tile ----
    #pragma unroll
    for (int it = 0; it < 4; it++) {
        int s = tid + it * 256;
        const float4* xp = (const float4*)(x + ((size_t)((b << 10) + s) << 6) + (h << 3));
        float4 xa = xp[0];
        float4 xb = xp[1];
        float c0 = __cosf(xa.x + ph0);
        float c1 = __cosf(xa.y + ph1);
        float c2 = __cosf(xa.z + ph2);
        float c3 = __cosf(xa.w + ph3);
        float c4 = __cosf(xb.x + ph4);
        float c5 = __cosf(xb.y + ph5);
        float c6 = __cosf(xb.z + ph6);
        float c7 = __cosf(xb.w + ph7);
        float p1 = c0 * c1;
        float p2 = p1 * c2;
        float p3 = p2 * c3;
        float p4 = p3 * c4;
        float p5 = p4 * c5;
        float p6 = p5 * c6;
        float p7 = p6 * c7;
        float t = c1 * c2;
        t *= c3; t *= c4; t *= c5; t *= c6; t *= c7;
        smt[0 * SS + s] = t;
        smt[1 * SS + s] = p1;
        smt[2 * SS + s] = p2;
        smt[3 * SS + s] = p3;
        smt[4 * SS + s] = p4;
        smt[5 * SS + s] = p5;
        smt[6 * SS + s] = p6;
        smt[7 * SS + s] = p7;
    }
    __syncthreads();

    // ---- per-thread q rows (scaled by 1/sqrt(8) * log2(e)) ----
    const float SC = 0.35355339059327373f * 1.4426950408889634f;
    const int r0 = blockIdx.y * 512 + tid * 2;
    const int r1 = r0 + 1;

    u64 Q0[8], Q1[8];                    // (q, q) broadcast pairs
    #pragma unroll
    for (int d = 0; d < 8; d++) {
        float a = smt[d * SS + r0] * SC;
        float bq = smt[d * SS + r1] * SC;
        Q0[d] = pk2(a, a);
        Q1[d] = pk2(bq, bq);
    }

    u64 A0[8], A1[8];                    // acc pairs: (even-j lane, odd-j lane)
    #pragma unroll
    for (int d = 0; d < 8; d++) { A0[d] = 0ull; A1[d] = 0ull; }
    u64 L0 = 0ull, L1 = 0ull;

    #pragma unroll 2
    for (int j = 0; j < SS; j += 4) {
        // K pairs: Ka[d] = (k[d][j], k[d][j+1]), Kb[d] = (k[d][j+2], k[d][j+3])
        u64 Ka[8], Kb[8];
        #pragma unroll
        for (int d = 0; d < 8; d++) {
            ulonglong2 kk = *(const ulonglong2*)&smt[d * SS + j];
            Ka[d] = kk.x;
            Kb[d] = kk.y;
        }

        // dots: 4 independent pair-chains of 8 fma2
        u64 Sa0 = fmul2(Q0[0], Ka[0]);
        u64 Sb0 = fmul2(Q0[0], Kb[0]);
        u64 Sa1 = fmul2(Q1[0], Ka[0]);
        u64 Sb1 = fmul2(Q1[0], Kb[0]);
        #pragma unroll
        for (int d = 1; d < 8; d++) {
            Sa0 = ffma2(Q0[d], Ka[d], Sa0);
            Sb0 = ffma2(Q0[d], Kb[d], Sb0);
            Sa1 = ffma2(Q1[d], Ka[d], Sa1);
            Sb1 = ffma2(Q1[d], Kb[d], Sb1);
        }

        float s00, s01, s02, s03, s10, s11, s12, s13;
        upk2(Sa0, s00, s01); upk2(Sb0, s02, s03);
        upk2(Sa1, s10, s11); upk2(Sb1, s12, s13);

        u64 Pa0 = pk2(ex2(s00), ex2(s01));
        u64 Pb0 = pk2(ex2(s02), ex2(s03));
        u64 Pa1 = pk2(ex2(s10), ex2(s11));
        u64 Pb1 = pk2(ex2(s12), ex2(s13));

        L0 = fadd2(L0, Pa0); L0 = fadd2(L0, Pb0);
        L1 = fadd2(L1, Pa1); L1 = fadd2(L1, Pb1);

        #pragma unroll
        for (int d = 0; d < 8; d++) {
            A0[d] = ffma2(Pa0, Ka[d], A0[d]);
            A0[d] = ffma2(Pb0, Kb[d], A0[d]);
            A1[d] = ffma2(Pa1, Ka[d], A1[d]);
            A1[d] = ffma2(Pb1, Kb[d], A1[d]);
        }
    }

    float l0a, l0b, l1a, l1b;
    upk2(L0, l0a, l0b);
    upk2(L1, l1a, l1b);
    float inv0 = 1.f / (l0a + l0b);
    float inv1 = 1.f / (l1a + l1b);

    float o0[8], o1[8];
    #pragma unroll
    for (int d = 0; d < 8; d++) {
        float xlo, xhi;
        upk2(A0[d], xlo, xhi); o0[d] = (xlo + xhi) * inv0;
        upk2(A1[d], xlo, xhi); o1[d] = (xlo + xhi) * inv1;
    }

    float4* ao4 = (float4*)&g_ao[((size_t)bh * SS + r0) * DK];
    ao4[0] = make_float4(o0[0], o0[1], o0[2], o0[3]);
    ao4[1] = make_float4(o0[4], o0[5], o0[6], o0[7]);
    ao4[2] = make_float4(o1[0], o1[1], o1[2], o1[3]);
    ao4[3] = make_float4(o1[4], o1[5], o1[6], o1[7]);
}

// ---------------------------------------------------------------------------
// Epilogue: gather heads + out = ao @ W^T + b.
// 256 threads = 4 rows x 64 outputs; W transposed in smem -> coalesced reads.
// ---------------------------------------------------------------------------
__global__ __launch_bounds__(256) void epilogue_kernel(const float* __restrict__ W,
                                                       const float* __restrict__ bias,
                                                       float* __restrict__ out) {
    __shared__ float sWt[64 * 64];
    __shared__ float sin_[4 * 64];

    int tid = threadIdx.x;
    for (int i = tid; i < 64 * 64; i += 256) {
        int e = i >> 6, f = i & 63;
        sWt[f * 64 + e] = W[i];
    }

    int row0 = blockIdx.x * 4;
    {
        int r = tid >> 6, f = tid & 63;
        int row = row0 + r;
        int b = row >> 10, s = row & 1023;
        sin_[tid] = g_ao[(((b * 8 + (f >> 3)) * 1024 + s) << 3) + (f & 7)];
    }
    __syncthreads();

    int r = tid >> 6, e = tid & 63;
    float acc = bias[e];
    #pragma unroll
    for (int f = 0; f < 64; f++)
        acc += sin_[r * 64 + f] * sWt[f * 64 + e];
    out[(row0 + r) * 64 + e] = acc;
}

// ---------------------------------------------------------------------------
extern "C" void kernel_launch(void* const* d_in, const int* in_sizes, int n_in,
                              void* d_out, int out_size) {
    const float* x    = (const float*)d_in[0];
    const float* phi  = (const float*)d_in[1];
    const float* W    = (const float*)d_in[2];
    const float* bias = (const float*)d_in[3];
    float* out = (float*)d_out;

    attn_kernel<<<dim3(BH, 2), 256>>>(x, phi);
    epilogue_kernel<<<(BB * SS) / 4, 256>>>(W, bias, out);
}

// round 4
// speedup vs baseline: 1.5507x; 1.4437x over previous
#include <cuda_runtime.h>

#define DK   8
#define SS   1024
#define BB   8
#define NH   8
#define BH   (BB * NH)          // 64

// Scratch: attention out in ROW-FEATURE layout [b*1024+s][h*8+d]  (2 MB)
__device__ float g_ao[BB * SS * 64];

// ---------------------------------------------------------------------------
// f32x2 packed-math helpers (sm_10x; untyped .b64 regs -> "l" constraints)
// ---------------------------------------------------------------------------
typedef unsigned long long u64;

__device__ __forceinline__ u64 ffma2(u64 a, u64 b, u64 c) {
    u64 r; asm("fma.rn.f32x2 %0,%1,%2,%3;" : "=l"(r) : "l"(a), "l"(b), "l"(c)); return r;
}
__device__ __forceinline__ u64 fmul2(u64 a, u64 b) {
    u64 r; asm("mul.rn.f32x2 %0,%1,%2;" : "=l"(r) : "l"(a), "l"(b)); return r;
}
__device__ __forceinline__ u64 fadd2(u64 a, u64 b) {
    u64 r; asm("add.rn.f32x2 %0,%1,%2;" : "=l"(r) : "l"(a), "l"(b)); return r;
}
__device__ __forceinline__ u64 pk2(float lo, float hi) {
    u64 r; asm("mov.b64 %0,{%1,%2};" : "=l"(r) : "f"(lo), "f"(hi)); return r;
}
__device__ __forceinline__ void upk2(u64 v, float& lo, float& hi) {
    asm("mov.b64 {%0,%1},%2;" : "=f"(lo), "=f"(hi) : "l"(v));
}
__device__ __forceinline__ float ex2(float x) {
    float r; asm("ex2.approx.f32 %0,%1;" : "=f"(r) : "f"(x)); return r;
}

// ---------------------------------------------------------------------------
// Fused qlayer + attention per (b,h).
//   qlayer == prefix products of cos(x+phi); K == V == proj;
//   |score| <= 2.83 -> plain sum-of-exp softmax; q pre-scaled by log2e/sqrt8.
//   K tile transposed in smem [d][j] -> key pairs are aligned f32x2 operands.
// Grid (64, 2), 512 threads, 1 q-row per thread (4 warps/SMSP for latency).
// ---------------------------------------------------------------------------
__global__ __launch_bounds__(512) void attn_kernel(const float* __restrict__ x,
                                                   const float* __restrict__ phi) {
    __shared__ float smt[8 * SS];        // 32 KB, smt[d*1024 + j]

    const int bh = blockIdx.x;
    const int b = bh >> 3, h = bh & 7;
    const int tid = threadIdx.x;

    float ph0 = phi[0], ph1 = phi[1], ph2 = phi[2], ph3 = phi[3];
    float ph4 = phi[4], ph5 = phi[5], ph6 = phi[6], ph7 = phi[7];

    // ---- prologue: quantum layer straight into transposed smem tile ----
    #pragma unroll
    for (int it = 0; it < 2; it++) {
        int s = tid + it * 512;
        const float4* xp = (const float4*)(x + ((size_t)((b << 10) + s) << 6) + (h << 3));
        float4 xa = xp[0];
        float4 xb = xp[1];
        float c0 = __cosf(xa.x + ph0);
        float c1 = __cosf(xa.y + ph1);
        float c2 = __cosf(xa.z + ph2);
        float c3 = __cosf(xa.w + ph3);
        float c4 = __cosf(xb.x + ph4);
        float c5 = __cosf(xb.y + ph5);
        float c6 = __cosf(xb.z + ph6);
        float c7 = __cosf(xb.w + ph7);
        float p1 = c0 * c1;
        float p2 = p1 * c2;
        float p3 = p2 * c3;
        float p4 = p3 * c4;
        float p5 = p4 * c5;
        float p6 = p5 * c6;
        float p7 = p6 * c7;
        float t = c1 * c2;
        t *= c3; t *= c4; t *= c5; t *= c6; t *= c7;
        smt[0 * SS + s] = t;
        smt[1 * SS + s] = p1;
        smt[2 * SS + s] = p2;
        smt[3 * SS + s] = p3;
        smt[4 * SS + s] = p4;
        smt[5 * SS + s] = p5;
        smt[6 * SS + s] = p6;
        smt[7 * SS + s] = p7;
    }
    __syncthreads();

    // ---- this thread's q row (scaled by 1/sqrt(8) * log2(e)) ----
    const float SC = 0.35355339059327373f * 1.4426950408889634f;
    const int s = blockIdx.y * 512 + tid;

    u64 Q[8];
    #pragma unroll
    for (int d = 0; d < 8; d++) {
        float q = smt[d * SS + s] * SC;
        Q[d] = pk2(q, q);
    }

    u64 A[8];
    #pragma unroll
    for (int d = 0; d < 8; d++) A[d] = 0ull;
    u64 L = 0ull;

    #pragma unroll 2
    for (int j = 0; j < SS; j += 4) {
        u64 Ka[8], Kb[8];
        #pragma unroll
        for (int d = 0; d < 8; d++) {
            ulonglong2 kk = *(const ulonglong2*)&smt[d * SS + j];
            Ka[d] = kk.x;
            Kb[d] = kk.y;
        }

        u64 Sa = fmul2(Q[0], Ka[0]);
        u64 Sb = fmul2(Q[0], Kb[0]);
        #pragma unroll
        for (int d = 1; d < 8; d++) {
            Sa = ffma2(Q[d], Ka[d], Sa);
            Sb = ffma2(Q[d], Kb[d], Sb);
        }

        float s0, s1, s2, s3;
        upk2(Sa, s0, s1);
        upk2(Sb, s2, s3);
        u64 Pa = pk2(ex2(s0), ex2(s1));
        u64 Pb = pk2(ex2(s2), ex2(s3));

        L = fadd2(L, Pa);
        L = fadd2(L, Pb);

        #pragma unroll
        for (int d = 0; d < 8; d++) {
            A[d] = ffma2(Pa, Ka[d], A[d]);
            A[d] = ffma2(Pb, Kb[d], A[d]);
        }
    }

    float la, lb;
    upk2(L, la, lb);
    float inv = 1.f / (la + lb);

    float o[8];
    #pragma unroll
    for (int d = 0; d < 8; d++) {
        float xlo, xhi;
        upk2(A[d], xlo, xhi);
        o[d] = (xlo + xhi) * inv;
    }

    // row-feature layout: one contiguous 32B sector per thread
    float4* ao4 = (float4*)&g_ao[(((size_t)b << 10) + s) * 64 + (h << 3)];
    ao4[0] = make_float4(o[0], o[1], o[2], o[3]);
    ao4[1] = make_float4(o[4], o[5], o[6], o[7]);
}

// ---------------------------------------------------------------------------
// Epilogue: out = ao @ W^T + b.  W rows live in REGISTERS (lane owns col e);
// activations staged linearly in smem, read via warp-broadcast ld.shared.v4.
// Block: 256 threads = 8 warps = 4 row-groups x 2 col-halves; 64 rows/block.
// ---------------------------------------------------------------------------
__global__ __launch_bounds__(256) void epilogue_kernel(const float* __restrict__ W,
                                                       const float* __restrict__ bias,
                                                       float* __restrict__ out) {
    __shared__ float ssin[64 * 64];      // 16 KB, rows linear

    const int tid = threadIdx.x;
    const int row0 = blockIdx.x * 64;

    // stage 64 rows of activations (perfectly linear)
    const float4* src = (const float4*)(g_ao + (size_t)row0 * 64);
    float4* dst = (float4*)ssin;
    #pragma unroll
    for (int i = 0; i < 4; i++)
        dst[tid + i * 256] = src[tid + i * 256];

    // this lane's output column + its W row in registers
    const int w = tid >> 5, lane = tid & 31;
    const int e = (w & 1) * 32 + lane;
    float wreg[64];
    const float4* wsrc = (const float4*)(W + e * 64);
    #pragma unroll
    for (int i = 0; i < 16; i++) {
        float4 v = wsrc[i];
        wreg[4 * i + 0] = v.x;
        wreg[4 * i + 1] = v.y;
        wreg[4 * i + 2] = v.z;
        wreg[4 * i + 3] = v.w;
    }
    const float be = bias[e];
    __syncthreads();

    const int rbase = (w >> 1) * 16;     // 16 rows per warp
    #pragma unroll 2
    for (int rr = 0; rr < 16; rr++) {
        int r = rbase + rr;
        const float4* srow = (const float4*)&ssin[r * 64];
        float acc = be;
        #pragma unroll
        for (int i = 0; i < 16; i++) {
            float4 sv = srow[i];         // broadcast: all lanes same address
            acc += sv.x * wreg[4 * i + 0];
            acc += sv.y * wreg[4 * i + 1];
            acc += sv.z * wreg[4 * i + 2];
            acc += sv.w * wreg[4 * i + 3];
        }
        out[(row0 + r) * 64 + e] = acc;  // lanes e consecutive -> coalesced
    }
}

// ---------------------------------------------------------------------------
extern "C" void kernel_launch(void* const* d_in, const int* in_sizes, int n_in,
                              void* d_out, int out_size) {
    const float* x    = (const float*)d_in[0];
    const float* phi  = (const float*)d_in[1];
    const float* W    = (const float*)d_in[2];
    const float* bias = (const float*)d_in[3];
    float* out = (float*)d_out;

    attn_kernel<<<dim3(BH, 2), 512>>>(x, phi);
    epilogue_kernel<<<(BB * SS) / 64, 256>>>(W, bias, out);
}